// round 1
// baseline (speedup 1.0000x reference)
#include <cuda_runtime.h>
#include <math.h>

#define BB 32
#define NN 512
#define NNODE (BB*NN)      // 16384
#define FF 6
#define WW 128
#define KG 100
#define KP 3
#define NEDGE (NNODE*KP)   // 49152
#define DIM2 1536

// ---------------- scratch (device globals; no allocation) ----------------
__device__ int   g_nbr100[NNODE*KG];
__device__ int   g_nbr3[NNODE*KP];
__device__ float g_t1[NNODE*18];
__device__ float g_hmA[NNODE*384];
__device__ float g_hmB[NNODE*384];
__device__ float g_Y[NNODE*384];
__device__ float g_Z[(size_t)NEDGE*256];
__device__ float g_M[(size_t)NEDGE*128];
__device__ float g_gram[(size_t)BB*NN*NN];
__device__ float g_z1[BB*DIM2];
__device__ float g_z2[BB*DIM2];

// ---------------- kNN: block-per-row, bitonic sort of 512 (d, idx) ----------------
__device__ __forceinline__ void cmpswap(float& ka, int& va, float& kb, int& vb, int ddd) {
    bool gt = (ka > kb) || (ka == kb && va > vb);
    if (gt == (ddd != 0)) {
        float tk = ka; ka = kb; kb = tk;
        int   tv = va; va = vb; vb = tv;
    }
}

__global__ void knn_kernel(const float* __restrict__ x, const float* __restrict__ gram,
                           int mode, int K, int* __restrict__ out) {
    __shared__ float key[512];
    __shared__ int   val[512];
    int node = blockIdx.x;
    int b = node >> 9;
    int i = node & 511;
    int tid = threadIdx.x;  // 256

    if (mode == 0) {
        float xi[FF];
        const float* xr = x + (size_t)node * FF;
        float sqi = 0.f;
#pragma unroll
        for (int d = 0; d < FF; d++) { xi[d] = xr[d]; sqi += xi[d]*xi[d]; }
        for (int j = tid; j < 512; j += 256) {
            const float* xj = x + (size_t)(b*512 + j) * FF;
            float dot = 0.f, sqj = 0.f;
#pragma unroll
            for (int d = 0; d < FF; d++) { float v = xj[d]; dot += xi[d]*v; sqj += v*v; }
            float dd = sqi + sqj - 2.f*dot;
            if (j == i) dd = 1e10f;
            key[j] = dd; val[j] = j;
        }
    } else {
        const float* g = gram + (size_t)b * 512 * 512;
        float gii = g[i*512 + i];
        for (int j = tid; j < 512; j += 256) {
            float dd = gii + g[j*512 + j] - 2.f*g[i*512 + j];
            if (j == i) dd = 1e10f;
            key[j] = dd; val[j] = j;
        }
    }
    __syncthreads();

    for (int size = 2; size < 512; size <<= 1) {
        int ddd = ((tid & (size >> 1)) == 0) ? 1 : 0;
        for (int stride = size >> 1; stride > 0; stride >>= 1) {
            int pos = 2*tid - (tid & (stride - 1));
            cmpswap(key[pos], val[pos], key[pos+stride], val[pos+stride], ddd);
            __syncthreads();
        }
    }
    for (int stride = 256; stride > 0; stride >>= 1) {
        int pos = 2*tid - (tid & (stride - 1));
        cmpswap(key[pos], val[pos], key[pos+stride], val[pos+stride], 1);
        __syncthreads();
    }
    for (int t = tid; t < K; t += 256)
        out[(size_t)node*K + t] = b*512 + val[t];   // global row index
}

// ---------------- neighbor mean aggregation ----------------
__global__ void aggr_mean(const float* __restrict__ src, int lds,
                          float* __restrict__ dst, int ldd,
                          const int* __restrict__ nbr, int k, int dim, float scale) {
    __shared__ int nb[128];
    int node = blockIdx.x;
    int tid = threadIdx.x;
    for (int t = tid; t < k; t += blockDim.x) nb[t] = nbr[(size_t)node*k + t];
    __syncthreads();
    if (tid < dim) {
        float s = 0.f;
#pragma unroll 4
        for (int t = 0; t < k; t++) s += src[(size_t)nb[t]*lds + tid];
        dst[(size_t)node*ldd + tid] = s * scale;
    }
}

// ---------------- fused GEMM: C = lrelu(A[M,K] @ W[K,128] + bias) ----------------
// BM=128, BN=128, BK=16, 256 threads, 8x8 per thread. M multiple of 128, N==128.
__global__ void gemm_bias_lrelu(const float* __restrict__ A, int lda,
                                const float* __restrict__ W,
                                const float* __restrict__ bias,
                                float* __restrict__ C, int ldc,
                                int K, int act) {
    __shared__ float As[16][136];
    __shared__ float Ws[16][128];
    int m0 = blockIdx.x * 128;
    int tid = threadIdx.x;
    int tr = tid >> 4, tc = tid & 15;
    float acc[8][8] = {};

    for (int k0 = 0; k0 < K; k0 += 16) {
#pragma unroll
        for (int i = 0; i < 8; i++) {
            int idx = tid + 256*i;
            int r = idx >> 4, c = idx & 15;
            float v = 0.f;
            if (k0 + c < K) v = A[(size_t)(m0 + r)*lda + k0 + c];
            As[c][r] = v;
        }
#pragma unroll
        for (int i = 0; i < 8; i++) {
            int idx = tid + 256*i;
            int kk = idx >> 7, n = idx & 127;
            float v = 0.f;
            if (k0 + kk < K) v = W[(size_t)(k0+kk)*128 + n];
            Ws[kk][n] = v;
        }
        __syncthreads();
#pragma unroll
        for (int k = 0; k < 16; k++) {
            float a[8], bv[8];
            *(float4*)&a[0]  = *(const float4*)&As[k][tr*8];
            *(float4*)&a[4]  = *(const float4*)&As[k][tr*8+4];
            *(float4*)&bv[0] = *(const float4*)&Ws[k][tc*8];
            *(float4*)&bv[4] = *(const float4*)&Ws[k][tc*8+4];
#pragma unroll
            for (int u = 0; u < 8; u++)
#pragma unroll
                for (int v = 0; v < 8; v++)
                    acc[u][v] = fmaf(a[u], bv[v], acc[u][v]);
        }
        __syncthreads();
    }
#pragma unroll
    for (int u = 0; u < 8; u++) {
        int r = m0 + tr*8 + u;
#pragma unroll
        for (int v = 0; v < 8; v++) {
            int c = tc*8 + v;
            float val = acc[u][v] + bias[c];
            if (act) val = val > 0.f ? val : 0.01f*val;
            C[(size_t)r*ldc + c] = val;
        }
    }
}

// ---------------- per-graph Gram matrix G = Y Y^T (512x512, K=128) ----------------
__global__ void gram_kernel(const float* __restrict__ Y, int ld, float* __restrict__ G) {
    __shared__ float Ai[16][68];
    __shared__ float Aj[16][68];
    int b  = blockIdx.z;
    int i0 = blockIdx.y * 64, j0 = blockIdx.x * 64;
    const float* Yb = Y + (size_t)b * 512 * ld;
    int tid = threadIdx.x;
    int ty = tid >> 4, tx = tid & 15;
    float acc[4][4] = {};

    for (int k0 = 0; k0 < 128; k0 += 16) {
#pragma unroll
        for (int t = 0; t < 4; t++) {
            int idx = tid + 256*t;
            int r = idx >> 4, c = idx & 15;
            Ai[c][r] = Yb[(size_t)(i0 + r)*ld + k0 + c];
            Aj[c][r] = Yb[(size_t)(j0 + r)*ld + k0 + c];
        }
        __syncthreads();
#pragma unroll
        for (int k = 0; k < 16; k++) {
            float a[4], bv[4];
            *(float4*)&a[0]  = *(const float4*)&Ai[k][ty*4];
            *(float4*)&bv[0] = *(const float4*)&Aj[k][tx*4];
#pragma unroll
            for (int u = 0; u < 4; u++)
#pragma unroll
                for (int v = 0; v < 4; v++)
                    acc[u][v] = fmaf(a[u], bv[v], acc[u][v]);
        }
        __syncthreads();
    }
    float* Gb = G + (size_t)b*512*512;
#pragma unroll
    for (int u = 0; u < 4; u++)
#pragma unroll
        for (int v = 0; v < 4; v++)
            Gb[(size_t)(i0+ty*4+u)*512 + (j0+tx*4+v)] = acc[u][v];
}

// ---------------- edge feature builders / max-pool ----------------
__global__ void build_z1(const float* __restrict__ x, const int* __restrict__ nbr100,
                         float* __restrict__ Z) {
    int e = blockIdx.x*blockDim.x + threadIdx.x;
    if (e >= NEDGE) return;
    int n = e / 3, k = e % 3;
    int j = nbr100[(size_t)n*KG + k];       // top-3 of sorted top-100 == kNN(k=3)
    const float* xi = x + (size_t)n*6;
    const float* xj = x + (size_t)j*6;
    float* z = Z + (size_t)e*12;
#pragma unroll
    for (int d = 0; d < 6; d++) { float a = xi[d], b = xj[d]; z[d] = a; z[6+d] = b - a; }
}

__global__ void build_z2(const float* __restrict__ Yc, const int* __restrict__ nbr3,
                         float* __restrict__ Z) {
    int n = blockIdx.x; int c = threadIdx.x;   // 128
    float yi = Yc[(size_t)n*384 + c];
#pragma unroll
    for (int k = 0; k < 3; k++) {
        int j = nbr3[n*3 + k];
        float yj = Yc[(size_t)j*384 + c];
        float* z = Z + (size_t)(n*3 + k)*256;
        z[c] = yi; z[128 + c] = yj - yi;
    }
}

__global__ void maxpool3(const float* __restrict__ M, float* __restrict__ Yc) {
    int n = blockIdx.x; int c = threadIdx.x;   // 128
    float v0 = M[(size_t)(n*3+0)*128 + c];
    float v1 = M[(size_t)(n*3+1)*128 + c];
    float v2 = M[(size_t)(n*3+2)*128 + c];
    Yc[(size_t)n*384 + c] = fmaxf(v0, fmaxf(v1, v2));
}

// ---------------- graph pooling (mean+max over 512 nodes) ----------------
__global__ void pool_mean_max(const float* __restrict__ src, int ld,
                              float* __restrict__ z, int offm, int offx) {
    int b = blockIdx.x; int c = threadIdx.x;   // 128
    const float* p = src + (size_t)b*512*ld + c;
    float s = 0.f, mx = -1e30f;
#pragma unroll 4
    for (int n = 0; n < 512; n++) { float v = p[(size_t)n*ld]; s += v; mx = fmaxf(mx, v); }
    z[b*DIM2 + offm + c] = s * (1.f/512.f);
    z[b*DIM2 + offx + c] = mx;
}

// ---------------- head: BatchNorm, 5x linear+lrelu, output ----------------
__global__ void bn_kernel(const float* __restrict__ zin, const float* __restrict__ gamma,
                          const float* __restrict__ beta, float* __restrict__ zout) {
    int c = blockIdx.x*blockDim.x + threadIdx.x;
    if (c >= DIM2) return;
    float s = 0.f;
    for (int r = 0; r < 32; r++) s += zin[r*DIM2 + c];
    float mu = s * (1.f/32.f);
    float v = 0.f;
    for (int r = 0; r < 32; r++) { float d = zin[r*DIM2+c] - mu; v += d*d; }
    float inv = rsqrtf(v*(1.f/32.f) + 1e-5f);
    float ga = gamma[c], be = beta[c];
    for (int r = 0; r < 32; r++)
        zout[r*DIM2+c] = (zin[r*DIM2+c] - mu)*inv*ga + be;
}

__global__ void lin_layer(const float* __restrict__ A, const float* __restrict__ W,
                          const float* __restrict__ bias, float* __restrict__ C) {
    extern __shared__ float As[];               // 32 x 1537
    int tid = threadIdx.x;                       // 512
    for (int idx = tid; idx < 32*1536; idx += 512) {
        int r = idx / 1536; int k = idx - r*1536;
        As[r*1537 + k] = A[idx];
    }
    __syncthreads();
    int c = blockIdx.x*16 + (tid & 15);
    int r = tid >> 4;                            // 0..31
    float acc = 0.f;
#pragma unroll 8
    for (int k = 0; k < 1536; k++)
        acc = fmaf(As[r*1537 + k], W[(size_t)k*1536 + c], acc);
    float v = acc + bias[c];
    v = v > 0.f ? v : 0.01f*v;
    C[r*DIM2 + c] = v;
}

__global__ void out_kernel(const float* __restrict__ z, const float* __restrict__ W,
                           const float* __restrict__ b, float* __restrict__ out) {
    __shared__ float red[256];
    int row = blockIdx.x; int tid = threadIdx.x;
    float s = 0.f;
    for (int k = tid; k < DIM2; k += 256) s += z[row*DIM2 + k] * W[k];
    red[tid] = s; __syncthreads();
    for (int o = 128; o > 0; o >>= 1) { if (tid < o) red[tid] += red[tid+o]; __syncthreads(); }
    if (tid == 0) out[row] = red[0] + b[0];
}

__global__ void copy6(const float* __restrict__ x, float* __restrict__ t1) {
    int idx = blockIdx.x*blockDim.x + threadIdx.x;
    if (idx >= NNODE*6) return;
    int n = idx / 6, d = idx - n*6;
    t1[n*18 + d] = x[idx];
}

// ---------------- host orchestration ----------------
extern "C" void kernel_launch(void* const* d_in, const int* in_sizes, int n_in,
                              void* d_out, int out_size) {
    const float* x       = (const float*)d_in[0];
    const float* tag1_W  = (const float*)d_in[2];
    const float* tag1_b  = (const float*)d_in[3];
    const float* tag_W   = (const float*)d_in[4];
    const float* tag_b   = (const float*)d_in[5];
    const float* p1_W1   = (const float*)d_in[6];
    const float* p1_b1   = (const float*)d_in[7];
    const float* p1_W2   = (const float*)d_in[8];
    const float* p1_b2   = (const float*)d_in[9];
    const float* pf_W    = (const float*)d_in[10];
    const float* pf_b    = (const float*)d_in[11];
    const float* bn_g    = (const float*)d_in[12];
    const float* bn_b    = (const float*)d_in[13];
    const float* lin_W   = (const float*)d_in[14];
    const float* lin_b   = (const float*)d_in[15];
    const float* out_W   = (const float*)d_in[16];
    const float* out_b   = (const float*)d_in[17];
    float* out = (float*)d_out;

    int *nbr100, *nbr3;
    float *t1, *hmA, *hmB, *Y, *Z, *M, *gram, *z1, *z2;
    cudaGetSymbolAddress((void**)&nbr100, g_nbr100);
    cudaGetSymbolAddress((void**)&nbr3,   g_nbr3);
    cudaGetSymbolAddress((void**)&t1,     g_t1);
    cudaGetSymbolAddress((void**)&hmA,    g_hmA);
    cudaGetSymbolAddress((void**)&hmB,    g_hmB);
    cudaGetSymbolAddress((void**)&Y,      g_Y);
    cudaGetSymbolAddress((void**)&Z,      g_Z);
    cudaGetSymbolAddress((void**)&M,      g_M);
    cudaGetSymbolAddress((void**)&gram,   g_gram);
    cudaGetSymbolAddress((void**)&z1,     g_z1);
    cudaGetSymbolAddress((void**)&z2,     g_z2);

    const float invKG = 1.f/(float)KG;

    // ===== graph kNN (k=100, sorted ascending -> top3 reusable) =====
    knn_kernel<<<NNODE, 256>>>(x, nullptr, 0, KG, nbr100);

    // ===== TAG layer 1 (F=6 -> 128) =====
    copy6<<<(NNODE*6 + 255)/256, 256>>>(x, t1);
    aggr_mean<<<NNODE, 32>>>(x, 6, t1 + 6, 18, nbr100, KG, 6, invKG);
    aggr_mean<<<NNODE, 32>>>(t1 + 6, 18, t1 + 12, 18, nbr100, KG, 6, invKG);
    gemm_bias_lrelu<<<NNODE/128, 256>>>(t1, 18, tag1_W, tag1_b, hmA, 384, 18, 1);
    pool_mean_max<<<32, 128>>>(hmA, 384, z1, 0, 128);

    // ===== TAG layer 2 (128 -> 128) =====
    aggr_mean<<<NNODE, 128>>>(hmA, 384, hmA + 128, 384, nbr100, KG, 128, invKG);
    aggr_mean<<<NNODE, 128>>>(hmA + 128, 384, hmA + 256, 384, nbr100, KG, 128, invKG);
    gemm_bias_lrelu<<<NNODE/128, 256>>>(hmA, 384, tag_W, tag_b, hmB, 384, 384, 1);
    pool_mean_max<<<32, 128>>>(hmB, 384, z1, 256, 384);

    // ===== TAG layer 3 (128 -> 128) =====
    aggr_mean<<<NNODE, 128>>>(hmB, 384, hmB + 128, 384, nbr100, KG, 128, invKG);
    aggr_mean<<<NNODE, 128>>>(hmB + 128, 384, hmB + 256, 384, nbr100, KG, 128, invKG);
    gemm_bias_lrelu<<<NNODE/128, 256>>>(hmB, 384, tag_W + 3*128*128, tag_b + 128, hmA, 384, 384, 1);
    pool_mean_max<<<32, 128>>>(hmA, 384, z1, 512, 640);

    // ===== EdgeConv 1 (on x, k=3, 2-layer MLP) =====
    build_z1<<<(NEDGE + 255)/256, 256>>>(x, nbr100, Z);
    gemm_bias_lrelu<<<NEDGE/128, 256>>>(Z, 12, p1_W1, p1_b1, M, 128, 12, 1);
    gemm_bias_lrelu<<<NEDGE/128, 256>>>(M, 128, p1_W2, p1_b2, Z, 128, 128, 1);
    maxpool3<<<NNODE, 128>>>(Z, Y);

    // ===== EdgeConv 2 (kNN on y1) =====
    gram_kernel<<<dim3(8,8,32), 256>>>(Y, 384, gram);
    knn_kernel<<<NNODE, 256>>>(nullptr, gram, 1, KP, nbr3);
    build_z2<<<NNODE, 128>>>(Y, nbr3, Z);
    gemm_bias_lrelu<<<NEDGE/128, 256>>>(Z, 256, pf_W, pf_b, M, 128, 256, 1);
    maxpool3<<<NNODE, 128>>>(M, Y + 128);

    // ===== EdgeConv 3 (kNN on y2) =====
    gram_kernel<<<dim3(8,8,32), 256>>>(Y + 128, 384, gram);
    knn_kernel<<<NNODE, 256>>>(nullptr, gram, 1, KP, nbr3);
    build_z2<<<NNODE, 128>>>(Y + 128, nbr3, Z);
    gemm_bias_lrelu<<<NEDGE/128, 256>>>(Z, 256, pf_W + 256*128, pf_b + 128, M, 128, 256, 1);
    maxpool3<<<NNODE, 128>>>(M, Y + 256);

    // ===== point-branch pooling =====
    pool_mean_max<<<32, 128>>>(Y,       384, z1, 768,        768 + 384);
    pool_mean_max<<<32, 128>>>(Y + 128, 384, z1, 768 + 128,  768 + 512);
    pool_mean_max<<<32, 128>>>(Y + 256, 384, z1, 768 + 256,  768 + 640);

    // ===== head =====
    bn_kernel<<<12, 128>>>(z1, bn_g, bn_b, z2);

    size_t shmem = 32*1537*sizeof(float);
    cudaFuncSetAttribute(lin_layer, cudaFuncAttributeMaxDynamicSharedMemorySize, (int)shmem);
    const float* src = z2; float* dst = z1;
    for (int g = 0; g < 5; g++) {
        lin_layer<<<96, 512, shmem>>>(src, lin_W + (size_t)g*1536*1536, lin_b + g*1536, dst);
        const float* tmp = dst; dst = (float*)src; src = tmp;
    }
    // after 5 layers result is in z1
    out_kernel<<<32, 256>>>(z1, out_W, out_b, out);
}

// round 2
// speedup vs baseline: 1.3484x; 1.3484x over previous
#include <cuda_runtime.h>
#include <cuda_fp16.h>
#include <math.h>

#define BB 32
#define NN 512
#define NNODE (BB*NN)      // 16384
#define FF 6
#define WW 128
#define KG 100
#define KP 3
#define NEDGE (NNODE*KP)   // 49152
#define DIM2 1536

// ---------------- scratch (device globals; no allocation) ----------------
__device__ int    g_nbr100[NNODE*KG];
__device__ int    g_nbr3[NNODE*KP];
__device__ float  g_t1[NNODE*18];
__device__ float  g_hmA[NNODE*384];
__device__ float  g_hmB[NNODE*384];
__device__ float  g_Y[NNODE*384];
__device__ float  g_Z[(size_t)NEDGE*256];
__device__ float  g_M[(size_t)NEDGE*128];
__device__ float  g_gram[(size_t)BB*NN*NN];
__device__ __half g_h16a[NNODE*128];
__device__ __half g_h16b[NNODE*128];
__device__ float  g_z1[BB*DIM2];
__device__ float  g_z2[BB*DIM2];

// ---------------- kNN (k=100): block-per-row bitonic sort of 512 (d, idx) ----------------
__device__ __forceinline__ void cmpswap(float& ka, int& va, float& kb, int& vb, int ddd) {
    bool gt = (ka > kb) || (ka == kb && va > vb);
    if (gt == (ddd != 0)) {
        float tk = ka; ka = kb; kb = tk;
        int   tv = va; va = vb; vb = tv;
    }
}

__global__ void knn_kernel(const float* __restrict__ x, int K, int* __restrict__ out) {
    __shared__ float key[512];
    __shared__ int   val[512];
    int node = blockIdx.x;
    int b = node >> 9;
    int i = node & 511;
    int tid = threadIdx.x;  // 256

    float xi[FF];
    const float* xr = x + (size_t)node * FF;
    float sqi = 0.f;
#pragma unroll
    for (int d = 0; d < FF; d++) { xi[d] = xr[d]; sqi += xi[d]*xi[d]; }
    for (int j = tid; j < 512; j += 256) {
        const float* xj = x + (size_t)(b*512 + j) * FF;
        float dot = 0.f, sqj = 0.f;
#pragma unroll
        for (int d = 0; d < FF; d++) { float v = xj[d]; dot += xi[d]*v; sqj += v*v; }
        float dd = sqi + sqj - 2.f*dot;
        if (j == i) dd = 1e10f;
        key[j] = dd; val[j] = j;
    }
    __syncthreads();

    for (int size = 2; size < 512; size <<= 1) {
        int ddd = ((tid & (size >> 1)) == 0) ? 1 : 0;
        for (int stride = size >> 1; stride > 0; stride >>= 1) {
            int pos = 2*tid - (tid & (stride - 1));
            cmpswap(key[pos], val[pos], key[pos+stride], val[pos+stride], ddd);
            __syncthreads();
        }
    }
    for (int stride = 256; stride > 0; stride >>= 1) {
        int pos = 2*tid - (tid & (stride - 1));
        cmpswap(key[pos], val[pos], key[pos+stride], val[pos+stride], 1);
        __syncthreads();
    }
    for (int t = tid; t < K; t += 256)
        out[(size_t)node*K + t] = b*512 + val[t];
}

// ---------------- top-3 from gram: 3-round argmin ----------------
__global__ void top3_kernel(const float* __restrict__ gram, int* __restrict__ out3) {
    __shared__ unsigned long long keys[512];
    __shared__ unsigned long long red[256];
    int node = blockIdx.x;
    int b = node >> 9, i = node & 511;
    int tid = threadIdx.x;  // 256
    const float* g = gram + (size_t)b*512*512;
    float gii = g[(size_t)i*512 + i];
    for (int j = tid; j < 512; j += 256) {
        float d = gii + g[(size_t)j*512 + j] - 2.f*g[(size_t)i*512 + j];
        if (j == i) d = 1e10f;
        unsigned int bits = __float_as_uint(d);
        bits = (bits & 0x80000000u) ? ~bits : (bits | 0x80000000u);
        keys[j] = ((unsigned long long)bits << 32) | (unsigned)j;
    }
    __syncthreads();
#pragma unroll
    for (int r = 0; r < 3; r++) {
        unsigned long long m = min(keys[tid], keys[tid+256]);
        red[tid] = m; __syncthreads();
        for (int o = 128; o > 0; o >>= 1) {
            if (tid < o) red[tid] = min(red[tid], red[tid+o]);
            __syncthreads();
        }
        unsigned long long best = red[0];
        int j = (int)(best & 0xffffffffu);
        if (tid == 0) {
            out3[node*3 + r] = b*512 + j;
            keys[j] = 0xFFFFFFFFFFFFFFFFull;
        }
        __syncthreads();
    }
}

// ---------------- TAG1: fused per-graph 2-hop mean of x (dim 6) ----------------
__global__ void tag1_aggr(const float* __restrict__ x, const int* __restrict__ nbr,
                          float* __restrict__ t1) {
    __shared__ float xs[6][512];
    __shared__ float m1[6][512];
    int b = blockIdx.x;
    int tid = threadIdx.x;  // 512
    const float* xr = x + (size_t)(b*512 + tid)*6;
#pragma unroll
    for (int d = 0; d < 6; d++) xs[d][tid] = xr[d];
    __syncthreads();

    const int* nb = nbr + (size_t)(b*512 + tid)*KG;
    float acc[6] = {};
#pragma unroll 4
    for (int k = 0; k < KG; k++) {
        int j = nb[k] & 511;
#pragma unroll
        for (int d = 0; d < 6; d++) acc[d] += xs[d][j];
    }
    float* tr = t1 + (size_t)(b*512 + tid)*18;
#pragma unroll
    for (int d = 0; d < 6; d++) {
        float v = acc[d] * 0.01f;
        m1[d][tid] = v;
        tr[d] = xs[d][tid];
        tr[6 + d] = v;
    }
    __syncthreads();
    float acc2[6] = {};
#pragma unroll 4
    for (int k = 0; k < KG; k++) {
        int j = nb[k] & 511;
#pragma unroll
        for (int d = 0; d < 6; d++) acc2[d] += m1[d][j];
    }
#pragma unroll
    for (int d = 0; d < 6; d++) tr[12 + d] = acc2[d] * 0.01f;
}

// ---------------- smem-staged fp16 aggregation (dim 128) ----------------
// grid (4, 32): 4 node-parts x 32 graphs; 1024 threads; dyn smem: tile + idxbuf
#define SMEM_AGG (512*128*2 + 32*100*4)
__global__ void aggr_smem(const __half* __restrict__ src16,
                          const int* __restrict__ nbr,
                          float* __restrict__ dst, int ldd,
                          __half* __restrict__ dst2, int wantHalf,
                          float scale) {
    extern __shared__ char sm[];
    __half* tile  = (__half*)sm;                 // [512][128]
    int*    idxbf = (int*)(sm + 512*128*2);      // [32][100]
    int bg = blockIdx.y, part = blockIdx.x;
    int tid = threadIdx.x;                        // 1024
    // load graph tile
    const uint4* gsrc = (const uint4*)(src16 + (size_t)bg*512*128);
    uint4* stile = (uint4*)tile;
#pragma unroll
    for (int t = 0; t < 8; t++) stile[tid + 1024*t] = gsrc[tid + 1024*t];
    __syncthreads();

    int warp = tid >> 5, lane = tid & 31;
    int* myidx = idxbf + warp*100;
#pragma unroll
    for (int nl = 0; nl < 4; nl++) {
        int nodeLocal = part*128 + warp*4 + nl;
        int node = bg*512 + nodeLocal;
        const int* nb = nbr + (size_t)node*KG;
        myidx[lane]      = nb[lane]      & 511;
        myidx[lane + 32] = nb[lane + 32] & 511;
        myidx[lane + 64] = nb[lane + 64] & 511;
        if (lane < 4) myidx[lane + 96] = nb[lane + 96] & 511;
        __syncwarp();
        float4 acc = {0.f, 0.f, 0.f, 0.f};
#pragma unroll 4
        for (int k = 0; k < KG; k++) {
            int j = myidx[k];
            const __half2* row = (const __half2*)tile + (size_t)j*64 + lane*2;
            float2 f0 = __half22float2(row[0]);
            float2 f1 = __half22float2(row[1]);
            acc.x += f0.x; acc.y += f0.y; acc.z += f1.x; acc.w += f1.y;
        }
        __syncwarp();
        acc.x *= scale; acc.y *= scale; acc.z *= scale; acc.w *= scale;
        *(float4*)(dst + (size_t)node*ldd + lane*4) = acc;
        if (wantHalf) {
            __half2* o = (__half2*)(dst2 + (size_t)node*128 + lane*4);
            o[0] = __floats2half2_rn(acc.x, acc.y);
            o[1] = __floats2half2_rn(acc.z, acc.w);
        }
    }
}

// ---------------- fused GEMM: C = act(A[M,K] @ W[K,128] + bias) ----------------
__global__ void gemm_bias_lrelu(const float* __restrict__ A, int lda,
                                const float* __restrict__ W,
                                const float* __restrict__ bias,
                                float* __restrict__ C, int ldc,
                                int K, int act, __half* __restrict__ C16) {
    __shared__ float As[16][136];
    __shared__ float Ws[16][128];
    int m0 = blockIdx.x * 128;
    int tid = threadIdx.x;
    int tr = tid >> 4, tc = tid & 15;
    float acc[8][8] = {};

    for (int k0 = 0; k0 < K; k0 += 16) {
#pragma unroll
        for (int i = 0; i < 8; i++) {
            int idx = tid + 256*i;
            int r = idx >> 4, c = idx & 15;
            float v = 0.f;
            if (k0 + c < K) v = A[(size_t)(m0 + r)*lda + k0 + c];
            As[c][r] = v;
        }
#pragma unroll
        for (int i = 0; i < 8; i++) {
            int idx = tid + 256*i;
            int kk = idx >> 7, n = idx & 127;
            float v = 0.f;
            if (k0 + kk < K) v = W[(size_t)(k0+kk)*128 + n];
            Ws[kk][n] = v;
        }
        __syncthreads();
#pragma unroll
        for (int k = 0; k < 16; k++) {
            float a[8], bv[8];
            *(float4*)&a[0]  = *(const float4*)&As[k][tr*8];
            *(float4*)&a[4]  = *(const float4*)&As[k][tr*8+4];
            *(float4*)&bv[0] = *(const float4*)&Ws[k][tc*8];
            *(float4*)&bv[4] = *(const float4*)&Ws[k][tc*8+4];
#pragma unroll
            for (int u = 0; u < 8; u++)
#pragma unroll
                for (int v = 0; v < 8; v++)
                    acc[u][v] = fmaf(a[u], bv[v], acc[u][v]);
        }
        __syncthreads();
    }
#pragma unroll
    for (int u = 0; u < 8; u++) {
        int r = m0 + tr*8 + u;
#pragma unroll
        for (int v = 0; v < 8; v++) {
            int c = tc*8 + v;
            float val = acc[u][v];
            if (bias) val += bias[c];
            if (act) val = val > 0.f ? val : 0.01f*val;
            C[(size_t)r*ldc + c] = val;
            if (C16) C16[(size_t)r*128 + c] = __float2half_rn(val);
        }
    }
}

// ---------------- per-graph Gram matrix G = Y Y^T (512x512, K=128) ----------------
__global__ void gram_kernel(const float* __restrict__ Y, int ld, float* __restrict__ G) {
    __shared__ float Ai[16][68];
    __shared__ float Aj[16][68];
    int b  = blockIdx.z;
    int i0 = blockIdx.y * 64, j0 = blockIdx.x * 64;
    const float* Yb = Y + (size_t)b * 512 * ld;
    int tid = threadIdx.x;
    int ty = tid >> 4, tx = tid & 15;
    float acc[4][4] = {};

    for (int k0 = 0; k0 < 128; k0 += 16) {
#pragma unroll
        for (int t = 0; t < 4; t++) {
            int idx = tid + 256*t;
            int r = idx >> 4, c = idx & 15;
            Ai[c][r] = Yb[(size_t)(i0 + r)*ld + k0 + c];
            Aj[c][r] = Yb[(size_t)(j0 + r)*ld + k0 + c];
        }
        __syncthreads();
#pragma unroll
        for (int k = 0; k < 16; k++) {
            float a[4], bv[4];
            *(float4*)&a[0]  = *(const float4*)&Ai[k][ty*4];
            *(float4*)&bv[0] = *(const float4*)&Aj[k][tx*4];
#pragma unroll
            for (int u = 0; u < 4; u++)
#pragma unroll
                for (int v = 0; v < 4; v++)
                    acc[u][v] = fmaf(a[u], bv[v], acc[u][v]);
        }
        __syncthreads();
    }
    float* Gb = G + (size_t)b*512*512;
#pragma unroll
    for (int u = 0; u < 4; u++)
#pragma unroll
        for (int v = 0; v < 4; v++)
            Gb[(size_t)(i0+ty*4+u)*512 + (j0+tx*4+v)] = acc[u][v];
}

// ---------------- EdgeConv1: U/V from x (K=6 each) ----------------
__global__ void uv6_kernel(const float* __restrict__ x, const float* __restrict__ W12,
                           float* __restrict__ U, float* __restrict__ V) {
    __shared__ float Ws[12][128];
    int tid = threadIdx.x;   // 256
    for (int t = tid; t < 12*128; t += 256) Ws[t >> 7][t & 127] = W12[t];
    __syncthreads();
    int node = blockIdx.x*2 + (tid >> 7);
    int c = tid & 127;
    const float* xr = x + (size_t)node*6;
    float au = 0.f, av = 0.f;
#pragma unroll
    for (int d = 0; d < 6; d++) {
        float xv = xr[d];
        au = fmaf(xv, Ws[d][c], au);
        av = fmaf(xv, Ws[6+d][c], av);
    }
    U[(size_t)node*128 + c] = au;
    V[(size_t)node*128 + c] = av;
}

// h_e = lrelu(U[i] + V[j] - V[i] + b), 3 edges per node
__global__ void edge_hidden(const float* __restrict__ U, const float* __restrict__ V,
                            const int* __restrict__ nbr, int nstride,
                            const float* __restrict__ b, float* __restrict__ H) {
    int n = blockIdx.x; int c = threadIdx.x;   // 128
    float base = U[(size_t)n*128 + c] - V[(size_t)n*128 + c] + b[c];
#pragma unroll
    for (int k = 0; k < 3; k++) {
        int j = nbr[(size_t)n*nstride + k];
        float h = base + V[(size_t)j*128 + c];
        H[(size_t)(n*3 + k)*128 + c] = h > 0.f ? h : 0.01f*h;
    }
}

// Y_out[n] = max_k lrelu(U[n] + V[j_k] - V[n] + b)
__global__ void edge_fused_max(const float* __restrict__ U, const float* __restrict__ V,
                               const int* __restrict__ nbr, int nstride,
                               const float* __restrict__ b, float* __restrict__ Yout) {
    int n = blockIdx.x; int c = threadIdx.x;   // 128
    float base = U[(size_t)n*128 + c] - V[(size_t)n*128 + c] + b[c];
    float m = -1e30f;
#pragma unroll
    for (int k = 0; k < 3; k++) {
        int j = nbr[(size_t)n*nstride + k];
        float h = base + V[(size_t)j*128 + c];
        h = h > 0.f ? h : 0.01f*h;
        m = fmaxf(m, h);
    }
    Yout[(size_t)n*384 + c] = m;
}

__global__ void maxpool3(const float* __restrict__ M, float* __restrict__ Yc) {
    int n = blockIdx.x; int c = threadIdx.x;   // 128
    float v0 = M[(size_t)(n*3+0)*128 + c];
    float v1 = M[(size_t)(n*3+1)*128 + c];
    float v2 = M[(size_t)(n*3+2)*128 + c];
    Yc[(size_t)n*384 + c] = fmaxf(v0, fmaxf(v1, v2));
}

// ---------------- graph pooling (mean+max over 512 nodes) ----------------
__global__ void pool_mean_max(const float* __restrict__ src, int ld,
                              float* __restrict__ z, int offm, int offx) {
    int b = blockIdx.x; int c = threadIdx.x;   // 128
    const float* p = src + (size_t)b*512*ld + c;
    float s = 0.f, mx = -1e30f;
#pragma unroll 4
    for (int n = 0; n < 512; n++) { float v = p[(size_t)n*ld]; s += v; mx = fmaxf(mx, v); }
    z[b*DIM2 + offm + c] = s * (1.f/512.f);
    z[b*DIM2 + offx + c] = mx;
}

// ---------------- head ----------------
__global__ void bn_kernel(const float* __restrict__ zin, const float* __restrict__ gamma,
                          const float* __restrict__ beta, float* __restrict__ zout) {
    int c = blockIdx.x*blockDim.x + threadIdx.x;
    if (c >= DIM2) return;
    float s = 0.f;
    for (int r = 0; r < 32; r++) s += zin[r*DIM2 + c];
    float mu = s * (1.f/32.f);
    float v = 0.f;
    for (int r = 0; r < 32; r++) { float d = zin[r*DIM2+c] - mu; v += d*d; }
    float inv = rsqrtf(v*(1.f/32.f) + 1e-5f);
    float ga = gamma[c], be = beta[c];
    for (int r = 0; r < 32; r++)
        zout[r*DIM2+c] = (zin[r*DIM2+c] - mu)*inv*ga + be;
}

__global__ void lin_layer(const float* __restrict__ A, const float* __restrict__ W,
                          const float* __restrict__ bias, float* __restrict__ C) {
    extern __shared__ float As[];               // 32 x 1537
    int tid = threadIdx.x;                       // 512
    for (int idx = tid; idx < 32*1536; idx += 512) {
        int r = idx / 1536; int k = idx - r*1536;
        As[r*1537 + k] = A[idx];
    }
    __syncthreads();
    int c = blockIdx.x*16 + (tid & 15);
    int r = tid >> 4;                            // 0..31
    float acc = 0.f;
#pragma unroll 8
    for (int k = 0; k < 1536; k++)
        acc = fmaf(As[r*1537 + k], W[(size_t)k*1536 + c], acc);
    float v = acc + bias[c];
    v = v > 0.f ? v : 0.01f*v;
    C[r*DIM2 + c] = v;
}

__global__ void out_kernel(const float* __restrict__ z, const float* __restrict__ W,
                           const float* __restrict__ b, float* __restrict__ out) {
    __shared__ float red[256];
    int row = blockIdx.x; int tid = threadIdx.x;
    float s = 0.f;
    for (int k = tid; k < DIM2; k += 256) s += z[row*DIM2 + k] * W[k];
    red[tid] = s; __syncthreads();
    for (int o = 128; o > 0; o >>= 1) { if (tid < o) red[tid] += red[tid+o]; __syncthreads(); }
    if (tid == 0) out[row] = red[0] + b[0];
}

// ---------------- host orchestration ----------------
extern "C" void kernel_launch(void* const* d_in, const int* in_sizes, int n_in,
                              void* d_out, int out_size) {
    const float* x       = (const float*)d_in[0];
    const float* tag1_W  = (const float*)d_in[2];
    const float* tag1_b  = (const float*)d_in[3];
    const float* tag_W   = (const float*)d_in[4];
    const float* tag_b   = (const float*)d_in[5];
    const float* p1_W1   = (const float*)d_in[6];
    const float* p1_b1   = (const float*)d_in[7];
    const float* p1_W2   = (const float*)d_in[8];
    const float* p1_b2   = (const float*)d_in[9];
    const float* pf_W    = (const float*)d_in[10];
    const float* pf_b    = (const float*)d_in[11];
    const float* bn_g    = (const float*)d_in[12];
    const float* bn_b    = (const float*)d_in[13];
    const float* lin_W   = (const float*)d_in[14];
    const float* lin_b   = (const float*)d_in[15];
    const float* out_W   = (const float*)d_in[16];
    const float* out_b   = (const float*)d_in[17];
    float* out = (float*)d_out;

    int *nbr100, *nbr3;
    float *t1, *hmA, *hmB, *Y, *Z, *M, *gram, *z1, *z2;
    __half *h16a, *h16b;
    cudaGetSymbolAddress((void**)&nbr100, g_nbr100);
    cudaGetSymbolAddress((void**)&nbr3,   g_nbr3);
    cudaGetSymbolAddress((void**)&t1,     g_t1);
    cudaGetSymbolAddress((void**)&hmA,    g_hmA);
    cudaGetSymbolAddress((void**)&hmB,    g_hmB);
    cudaGetSymbolAddress((void**)&Y,      g_Y);
    cudaGetSymbolAddress((void**)&Z,      g_Z);
    cudaGetSymbolAddress((void**)&M,      g_M);
    cudaGetSymbolAddress((void**)&gram,   g_gram);
    cudaGetSymbolAddress((void**)&h16a,   g_h16a);
    cudaGetSymbolAddress((void**)&h16b,   g_h16b);
    cudaGetSymbolAddress((void**)&z1,     g_z1);
    cudaGetSymbolAddress((void**)&z2,     g_z2);

    cudaFuncSetAttribute(aggr_smem, cudaFuncAttributeMaxDynamicSharedMemorySize, SMEM_AGG);
    size_t shmem_lin = 32*1537*sizeof(float);
    cudaFuncSetAttribute(lin_layer, cudaFuncAttributeMaxDynamicSharedMemorySize, (int)shmem_lin);

    const float invKG = 1.f/(float)KG;
    dim3 gAgg(4, 32);

    // ===== graph kNN (k=100, sorted ascending; top3 = EdgeConv1 nbrs) =====
    knn_kernel<<<NNODE, 256>>>(x, KG, nbr100);

    // ===== TAG layer 1 (F=6 -> 128) =====
    tag1_aggr<<<32, 512>>>(x, nbr100, t1);
    gemm_bias_lrelu<<<NNODE/128, 256>>>(t1, 18, tag1_W, tag1_b, hmA, 384, 18, 1, h16a);
    pool_mean_max<<<32, 128>>>(hmA, 384, z1, 0, 128);

    // ===== TAG layer 2 (128 -> 128) =====
    aggr_smem<<<gAgg, 1024, SMEM_AGG>>>(h16a, nbr100, hmA + 128, 384, h16b, 1, invKG);
    aggr_smem<<<gAgg, 1024, SMEM_AGG>>>(h16b, nbr100, hmA + 256, 384, nullptr, 0, invKG);
    gemm_bias_lrelu<<<NNODE/128, 256>>>(hmA, 384, tag_W, tag_b, hmB, 384, 384, 1, h16a);
    pool_mean_max<<<32, 128>>>(hmB, 384, z1, 256, 384);

    // ===== TAG layer 3 (128 -> 128) =====
    aggr_smem<<<gAgg, 1024, SMEM_AGG>>>(h16a, nbr100, hmB + 128, 384, h16b, 1, invKG);
    aggr_smem<<<gAgg, 1024, SMEM_AGG>>>(h16b, nbr100, hmB + 256, 384, nullptr, 0, invKG);
    gemm_bias_lrelu<<<NNODE/128, 256>>>(hmB, 384, tag_W + 3*128*128, tag_b + 128, hmA, 384, 384, 1, nullptr);
    pool_mean_max<<<32, 128>>>(hmA, 384, z1, 512, 640);

    // ===== EdgeConv 1 (on x, k=3, 2-layer MLP; layer1 linearized) =====
    {
        float* U = M;
        float* V = M + (size_t)NNODE*128;
        uv6_kernel<<<NNODE/2, 256>>>(x, p1_W1, U, V);
        edge_hidden<<<NNODE, 128>>>(U, V, nbr100, KG, p1_b1, Z);
    }
    gemm_bias_lrelu<<<NEDGE/128, 256>>>(Z, 128, p1_W2, p1_b2, M, 128, 128, 1, nullptr);
    maxpool3<<<NNODE, 128>>>(M, Y);

    // ===== EdgeConv 2 (kNN on y1, linearized) =====
    gram_kernel<<<dim3(8,8,32), 256>>>(Y, 384, gram);
    top3_kernel<<<NNODE, 256>>>(gram, nbr3);
    {
        float* U = Z;
        float* V = Z + (size_t)NNODE*128;
        gemm_bias_lrelu<<<NNODE/128, 256>>>(Y, 384, pf_W,            nullptr, U, 128, 128, 0, nullptr);
        gemm_bias_lrelu<<<NNODE/128, 256>>>(Y, 384, pf_W + 128*128,  nullptr, V, 128, 128, 0, nullptr);
        edge_fused_max<<<NNODE, 128>>>(U, V, nbr3, KP, pf_b, Y + 128);
    }

    // ===== EdgeConv 3 (kNN on y2, linearized) =====
    gram_kernel<<<dim3(8,8,32), 256>>>(Y + 128, 384, gram);
    top3_kernel<<<NNODE, 256>>>(gram, nbr3);
    {
        float* U = Z;
        float* V = Z + (size_t)NNODE*128;
        gemm_bias_lrelu<<<NNODE/128, 256>>>(Y + 128, 384, pf_W + 256*128,          nullptr, U, 128, 128, 0, nullptr);
        gemm_bias_lrelu<<<NNODE/128, 256>>>(Y + 128, 384, pf_W + 256*128 + 128*128, nullptr, V, 128, 128, 0, nullptr);
        edge_fused_max<<<NNODE, 128>>>(U, V, nbr3, KP, pf_b + 128, Y + 256);
    }

    // ===== point-branch pooling =====
    pool_mean_max<<<32, 128>>>(Y,       384, z1, 768,        768 + 384);
    pool_mean_max<<<32, 128>>>(Y + 128, 384, z1, 768 + 128,  768 + 512);
    pool_mean_max<<<32, 128>>>(Y + 256, 384, z1, 768 + 256,  768 + 640);

    // ===== head =====
    bn_kernel<<<12, 128>>>(z1, bn_g, bn_b, z2);

    const float* src = z2; float* dst = z1;
    for (int g = 0; g < 5; g++) {
        lin_layer<<<96, 512, shmem_lin>>>(src, lin_W + (size_t)g*1536*1536, lin_b + g*1536, dst);
        const float* tmp = dst; dst = (float*)src; src = tmp;
    }
    out_kernel<<<32, 256>>>(z1, out_W, out_b, out);
}